// round 2
// baseline (speedup 1.0000x reference)
#include <cuda_runtime.h>

// GRAPE layer: h_new = relu([h, mean_agg] @ Q + qb); e_new = relu([e, h_u, h_v] @ W + wb)
// messages = relu([h_u, e] @ P + pb), mean-aggregated onto target nodes.

#define NNODES 100000
#define NEDGES 625000
#define DIM 128
#define BE 64          // rows (edges/nodes) per CTA tile
#define KC 32          // K chunk
#define XPITCH (KC + 1)
#define NTHREADS 256

// Scratch (allocation-free rule: __device__ globals)
__device__ float g_agg[(size_t)NNODES * DIM];
__device__ float g_deg[NNODES];
__device__ int   g_src[NEDGES];
__device__ int   g_tgt[NEDGES];
__device__ int   g_is64;

// ---- packed f32x2 helpers (Blackwell dual-rate FFMA, PTX-only) ----
__device__ __forceinline__ unsigned long long pack2(float x) {
    unsigned long long r;
    asm("mov.b64 %0, {%1, %1};" : "=l"(r) : "f"(x));
    return r;
}
__device__ __forceinline__ void ffma2(unsigned long long &c, unsigned long long a,
                                      unsigned long long b) {
    asm("fma.rn.f32x2 %0, %1, %2, %0;" : "+l"(c) : "l"(a), "l"(b));
}
__device__ __forceinline__ float2 unpack2(unsigned long long v) {
    float2 r;
    asm("mov.b64 {%0, %1}, %2;" : "=f"(r.x), "=f"(r.y) : "l"(v));
    return r;
}

// ---------------- index dtype detection + decode ----------------
// JAX with x64 disabled silently downcasts the reference's int64 edge_index to
// int32. Detect which layout we actually got: reading int32 pairs as int64
// yields values >= NNODES with overwhelming probability.
__global__ void detect_idx(const void* ei) {
    if (threadIdx.x == 0 && blockIdx.x == 0) {
        const unsigned long long* p = (const unsigned long long*)ei;
        int is64 = 1;
        for (int i = 0; i < 64; ++i)
            if (p[i] >= (unsigned long long)NNODES) { is64 = 0; break; }
        g_is64 = is64;
    }
}

__global__ void decode_idx(const void* ei) {
    int i = blockIdx.x * blockDim.x + threadIdx.x;
    // zero aggregation scratch in the same pass (grid sized for N*DIM)
    size_t stride = (size_t)gridDim.x * blockDim.x;
    for (size_t j = i; j < (size_t)NNODES * DIM; j += stride) g_agg[j] = 0.f;
    for (size_t j = i; j < NNODES; j += stride) g_deg[j] = 0.f;
    if (i < NEDGES) {
        long long s, t;
        if (g_is64) {
            s = ((const long long*)ei)[i];
            t = ((const long long*)ei)[NEDGES + i];
        } else {
            s = ((const int*)ei)[i];
            t = ((const int*)ei)[NEDGES + i];
        }
        if (s < 0) s = 0; if (s >= NNODES) s = NNODES - 1;
        if (t < 0) t = 0; if (t >= NNODES) t = NNODES - 1;
        g_src[i] = (int)s;
        g_tgt[i] = (int)t;
    }
}

__global__ void count_deg() {
    int i = blockIdx.x * blockDim.x + threadIdx.x;
    if (i < NEDGES) atomicAdd(&g_deg[g_tgt[i]], 1.f);
}

// Consume one KC x 128 chunk: Xs [BE][XPITCH], W2 = 64-bit view of Ws[KC][128].
// Thread (cx, ry) owns rows {ry+16r} x float2-cols {cx+16c}.
__device__ __forceinline__ void mm_chunk(const float* __restrict__ Xs,
                                         const unsigned long long* __restrict__ W2,
                                         int ry, int cx, unsigned long long acc[4][4]) {
#pragma unroll 8
    for (int k = 0; k < KC; ++k) {
        unsigned long long a2[4];
#pragma unroll
        for (int r = 0; r < 4; ++r)
            a2[r] = pack2(Xs[(ry + 16 * r) * XPITCH + k]);
#pragma unroll
        for (int c = 0; c < 4; ++c) {
            unsigned long long b2 = W2[k * (DIM / 2) + cx + 16 * c];
#pragma unroll
            for (int r = 0; r < 4; ++r) ffma2(acc[r][c], a2[r], b2);
        }
    }
}

// ---------------- Kernel 1: message MLP + scatter-add ----------------
__global__ __launch_bounds__(NTHREADS, 2) void k_edge_msg(
    const float* __restrict__ h, const float* __restrict__ e,
    const float* __restrict__ Pw, const float* __restrict__ Pb)
{
    __shared__ float S[BE * DIM];
    __shared__ int Ssrc[BE], Stgt[BE];
    float* Xs = S;
    float* Wf = S + BE * XPITCH;                       // byte off 8448: 16B aligned
    const unsigned long long* W2 = (const unsigned long long*)Wf;

    const int tid = threadIdx.x;
    const int e0 = blockIdx.x * BE;

    if (tid < BE) {
        int eg = e0 + tid;
        Ssrc[tid] = (eg < NEDGES) ? g_src[eg] : 0;
    } else if (tid < 2 * BE) {
        int eg = e0 + (tid - BE);
        Stgt[tid - BE] = (eg < NEDGES) ? g_tgt[eg] : 0;
    }

    const int cx = tid & 15, ry = tid >> 4;
    unsigned long long acc[4][4];
#pragma unroll
    for (int r = 0; r < 4; ++r)
#pragma unroll
        for (int c = 0; c < 4; ++c) acc[r][c] = 0ull;

    const int lrow = tid >> 2, lq = tid & 3;           // X loader: 4 thr/row, 8 floats each
    const int wk = tid >> 3, wpart = tid & 7;          // W loader: 32 rows, 16 floats each
    const int leg = e0 + lrow;
    const int legc = (leg < NEDGES) ? leg : 0;

    __syncthreads();
    const float* xbase0 = h + (size_t)Ssrc[lrow] * DIM;   // segment 0: h_u
    const float* xbase1 = e + (size_t)legc * DIM;         // segment 1: e

#pragma unroll 1
    for (int seg = 0; seg < 2; ++seg) {
        const float* xb = (seg == 0) ? xbase0 : xbase1;
        const float* wb = Pw + (size_t)(seg * DIM) * DIM;
#pragma unroll 1
        for (int kc = 0; kc < DIM; kc += KC) {
            float4 v0 = *(const float4*)(xb + kc + lq * 8);
            float4 v1 = *(const float4*)(xb + kc + lq * 8 + 4);
            const float4* wp = (const float4*)(wb + (size_t)(kc + wk) * DIM + wpart * 16);
            float4 w0 = wp[0], w1 = wp[1], w2 = wp[2], w3 = wp[3];
            float* xd = Xs + lrow * XPITCH + lq * 8;
            xd[0]=v0.x; xd[1]=v0.y; xd[2]=v0.z; xd[3]=v0.w;
            xd[4]=v1.x; xd[5]=v1.y; xd[6]=v1.z; xd[7]=v1.w;
            float4* wd = (float4*)(Wf + wk * DIM + wpart * 16);
            wd[0]=w0; wd[1]=w1; wd[2]=w2; wd[3]=w3;
            __syncthreads();
            mm_chunk(Xs, W2, ry, cx, acc);
            __syncthreads();
        }
    }

    float2 bias[4];
#pragma unroll
    for (int c = 0; c < 4; ++c) bias[c] = *(const float2*)(Pb + 2 * (cx + 16 * c));

#pragma unroll
    for (int r = 0; r < 4; ++r) {
        const int lr = ry + 16 * r;
        const int eg = e0 + lr;
        if (eg < NEDGES) {
            const int tgt = Stgt[lr];
            float* arow = g_agg + (size_t)tgt * DIM;
#pragma unroll
            for (int c = 0; c < 4; ++c) {
                float2 v = unpack2(acc[r][c]);
                v.x = fmaxf(v.x + bias[c].x, 0.f);
                v.y = fmaxf(v.y + bias[c].y, 0.f);
                atomicAdd((float2*)(arow + 2 * (cx + 16 * c)), v);
            }
        }
    }
}

// ---------------- Kernel 2: edge update MLP ----------------
__global__ __launch_bounds__(NTHREADS, 2) void k_edge_upd(
    const float* __restrict__ h, const float* __restrict__ e,
    const float* __restrict__ Ww, const float* __restrict__ Wb,
    float* __restrict__ oute)
{
    __shared__ float S[BE * DIM];
    __shared__ int Ssrc[BE], Stgt[BE];
    float* Xs = S;
    float* Wf = S + BE * XPITCH;
    const unsigned long long* W2 = (const unsigned long long*)Wf;

    const int tid = threadIdx.x;
    const int e0 = blockIdx.x * BE;

    if (tid < BE) {
        int eg = e0 + tid;
        Ssrc[tid] = (eg < NEDGES) ? g_src[eg] : 0;
    } else if (tid < 2 * BE) {
        int eg = e0 + (tid - BE);
        Stgt[tid - BE] = (eg < NEDGES) ? g_tgt[eg] : 0;
    }

    const int cx = tid & 15, ry = tid >> 4;
    unsigned long long acc[4][4];
#pragma unroll
    for (int r = 0; r < 4; ++r)
#pragma unroll
        for (int c = 0; c < 4; ++c) acc[r][c] = 0ull;

    const int lrow = tid >> 2, lq = tid & 3;
    const int wk = tid >> 3, wpart = tid & 7;
    const int leg = e0 + lrow;
    const int legc = (leg < NEDGES) ? leg : 0;

    __syncthreads();
    const float* xbase0 = e + (size_t)legc * DIM;          // segment 0: e
    const float* xbase1 = h + (size_t)Ssrc[lrow] * DIM;    // segment 1: h_u
    const float* xbase2 = h + (size_t)Stgt[lrow] * DIM;    // segment 2: h_v

#pragma unroll 1
    for (int seg = 0; seg < 3; ++seg) {
        const float* xb = (seg == 0) ? xbase0 : (seg == 1) ? xbase1 : xbase2;
        const float* wb = Ww + (size_t)(seg * DIM) * DIM;
#pragma unroll 1
        for (int kc = 0; kc < DIM; kc += KC) {
            float4 v0 = *(const float4*)(xb + kc + lq * 8);
            float4 v1 = *(const float4*)(xb + kc + lq * 8 + 4);
            const float4* wp = (const float4*)(wb + (size_t)(kc + wk) * DIM + wpart * 16);
            float4 w0 = wp[0], w1 = wp[1], w2 = wp[2], w3 = wp[3];
            float* xd = Xs + lrow * XPITCH + lq * 8;
            xd[0]=v0.x; xd[1]=v0.y; xd[2]=v0.z; xd[3]=v0.w;
            xd[4]=v1.x; xd[5]=v1.y; xd[6]=v1.z; xd[7]=v1.w;
            float4* wd = (float4*)(Wf + wk * DIM + wpart * 16);
            wd[0]=w0; wd[1]=w1; wd[2]=w2; wd[3]=w3;
            __syncthreads();
            mm_chunk(Xs, W2, ry, cx, acc);
            __syncthreads();
        }
    }

    float2 bias[4];
#pragma unroll
    for (int c = 0; c < 4; ++c) bias[c] = *(const float2*)(Wb + 2 * (cx + 16 * c));

    // Stage tile through smem for coalesced stores
#pragma unroll
    for (int r = 0; r < 4; ++r) {
        const int lr = ry + 16 * r;
#pragma unroll
        for (int c = 0; c < 4; ++c) {
            float2 v = unpack2(acc[r][c]);
            v.x = fmaxf(v.x + bias[c].x, 0.f);
            v.y = fmaxf(v.y + bias[c].y, 0.f);
            *(float2*)(S + lr * DIM + 2 * (cx + 16 * c)) = v;
        }
    }
    __syncthreads();
    const int orow = e0 + lrow;
    if (orow < NEDGES) {
        float4* dst = (float4*)(oute + (size_t)orow * DIM + lq * 32);
        const float4* ssrc = (const float4*)(S + lrow * DIM + lq * 32);
#pragma unroll
        for (int i = 0; i < 8; ++i) dst[i] = ssrc[i];
    }
}

// ---------------- Kernel 3: node update MLP ----------------
__global__ __launch_bounds__(NTHREADS, 2) void k_node(
    const float* __restrict__ h,
    const float* __restrict__ Qw, const float* __restrict__ Qb,
    float* __restrict__ outh)
{
    __shared__ float S[BE * DIM];
    float* Xs = S;
    float* Wf = S + BE * XPITCH;
    const unsigned long long* W2 = (const unsigned long long*)Wf;

    const int tid = threadIdx.x;
    const int n0 = blockIdx.x * BE;
    const int cx = tid & 15, ry = tid >> 4;

    unsigned long long acc[4][4];
#pragma unroll
    for (int r = 0; r < 4; ++r)
#pragma unroll
        for (int c = 0; c < 4; ++c) acc[r][c] = 0ull;

    const int lrow = tid >> 2, lq = tid & 3;
    const int wk = tid >> 3, wpart = tid & 7;
    const int node = n0 + lrow;
    const int nodec = (node < NNODES) ? node : (NNODES - 1);
    const float invdeg = 1.f / fmaxf(g_deg[nodec], 1.f);

#pragma unroll 1
    for (int seg = 0; seg < 2; ++seg) {
        const float* xb = (seg == 0) ? (h + (size_t)nodec * DIM)
                                     : (g_agg + (size_t)nodec * DIM);
        const float scale = (seg == 0) ? 1.f : invdeg;
        const float* wb = Qw + (size_t)(seg * DIM) * DIM;
#pragma unroll 1
        for (int kc = 0; kc < DIM; kc += KC) {
            float4 v0 = *(const float4*)(xb + kc + lq * 8);
            float4 v1 = *(const float4*)(xb + kc + lq * 8 + 4);
            const float4* wp = (const float4*)(wb + (size_t)(kc + wk) * DIM + wpart * 16);
            float4 w0 = wp[0], w1 = wp[1], w2 = wp[2], w3 = wp[3];
            float* xd = Xs + lrow * XPITCH + lq * 8;
            xd[0]=v0.x*scale; xd[1]=v0.y*scale; xd[2]=v0.z*scale; xd[3]=v0.w*scale;
            xd[4]=v1.x*scale; xd[5]=v1.y*scale; xd[6]=v1.z*scale; xd[7]=v1.w*scale;
            float4* wd = (float4*)(Wf + wk * DIM + wpart * 16);
            wd[0]=w0; wd[1]=w1; wd[2]=w2; wd[3]=w3;
            __syncthreads();
            mm_chunk(Xs, W2, ry, cx, acc);
            __syncthreads();
        }
    }

    float2 bias[4];
#pragma unroll
    for (int c = 0; c < 4; ++c) bias[c] = *(const float2*)(Qb + 2 * (cx + 16 * c));

#pragma unroll
    for (int r = 0; r < 4; ++r) {
        const int lr = ry + 16 * r;
#pragma unroll
        for (int c = 0; c < 4; ++c) {
            float2 v = unpack2(acc[r][c]);
            v.x = fmaxf(v.x + bias[c].x, 0.f);
            v.y = fmaxf(v.y + bias[c].y, 0.f);
            *(float2*)(S + lr * DIM + 2 * (cx + 16 * c)) = v;
        }
    }
    __syncthreads();
    const int orow = n0 + lrow;
    if (orow < NNODES) {
        float4* dst = (float4*)(outh + (size_t)orow * DIM + lq * 32);
        const float4* ssrc = (const float4*)(S + lrow * DIM + lq * 32);
#pragma unroll
        for (int i = 0; i < 8; ++i) dst[i] = ssrc[i];
    }
}

extern "C" void kernel_launch(void* const* d_in, const int* in_sizes, int n_in,
                              void* d_out, int out_size) {
    const float* h    = (const float*)d_in[0];
    const float* e    = (const float*)d_in[1];
    const void*  eidx = d_in[2];
    const float* Pw   = (const float*)d_in[3];
    const float* Pb   = (const float*)d_in[4];
    const float* Qw   = (const float*)d_in[5];
    const float* Qb   = (const float*)d_in[6];
    const float* Ww   = (const float*)d_in[7];
    const float* Wb   = (const float*)d_in[8];

    float* outh = (float*)d_out;                       // h_new: [N,128] first
    float* oute = outh + (size_t)NNODES * DIM;         // e_new: [E,128] after

    const int eblocks = (NEDGES + BE - 1) / BE;
    const int nblocks = (NNODES + BE - 1) / BE;
    const int dblocks = (NEDGES + 255) / 256;

    detect_idx<<<1, 32>>>(eidx);
    decode_idx<<<dblocks, 256>>>(eidx);
    count_deg<<<dblocks, 256>>>();
    k_edge_msg<<<eblocks, NTHREADS>>>(h, e, Pw, Pb);
    k_node<<<nblocks, NTHREADS>>>(h, Qw, Qb, outh);
    k_edge_upd<<<eblocks, NTHREADS>>>(h, e, Ww, Wb, oute);
}

// round 5
// speedup vs baseline: 2.7093x; 2.7093x over previous
#include <cuda_runtime.h>
#include <cstdint>

#define NNODES 100000
#define NEDGES 625000
#define DIM 128

// ---- smem layout (dynamic, exactly 48KB -> no opt-in attribute needed) ----
#define A_HI_OFF 0          // 64 rows x 128B (bf16 k-major, swizzled)
#define A_LO_OFF 8192
#define B_HI_OFF 16384      // 128 n-rows x 128B (k-major, swizzled)
#define B_LO_OFF 32768
#define SMEM_BYTES 49152

// ---- device scratch (allocation-free rule) ----
__device__ float g_agg[(size_t)NNODES * DIM];
__device__ float g_deg[NNODES];
__device__ int g_src[NEDGES];
__device__ int g_tgt[NEDGES];
__device__ int g_is64;
__device__ uint32_t g_h_hi[(size_t)NNODES * 64];   // bf16x2-packed h (hi part)
__device__ uint32_t g_h_lo[(size_t)NNODES * 64];
__device__ uint32_t g_imgP_hi[4 * 4096], g_imgP_lo[4 * 4096];  // swizzled weight images
__device__ uint32_t g_imgQ_hi[4 * 4096], g_imgQ_lo[4 * 4096];
__device__ uint32_t g_imgW_hi[6 * 4096], g_imgW_lo[6 * 4096];

// ================= helpers =================
__device__ __forceinline__ uint32_t smem_u32(const void* p) {
    uint32_t a;
    asm("{ .reg .u64 t; cvta.to.shared.u64 t, %1; cvt.u32.u64 %0, t; }" : "=r"(a) : "l"(p));
    return a;
}
// hi/lo bf16 split of packed pair (x,y); low 16 bits of word = bf16(x)
__device__ __forceinline__ void cvt_pair(float x, float y, uint32_t& hi, uint32_t& lo) {
    asm("cvt.rn.bf16x2.f32 %0, %2, %1;" : "=r"(hi) : "f"(x), "f"(y));
    float fx = __uint_as_float(hi << 16);
    float fy = __uint_as_float(hi & 0xffff0000u);
    float rx = x - fx, ry = y - fy;
    asm("cvt.rn.bf16x2.f32 %0, %2, %1;" : "=r"(lo) : "f"(rx), "f"(ry));
}
__device__ __forceinline__ void ldsm_x4(uint32_t* r, uint32_t addr) {
    asm volatile("ldmatrix.sync.aligned.m8n8.x4.shared.b16 {%0,%1,%2,%3}, [%4];"
                 : "=r"(r[0]), "=r"(r[1]), "=r"(r[2]), "=r"(r[3]) : "r"(addr));
}
__device__ __forceinline__ void ldsm_x2(uint32_t* r, uint32_t addr) {
    asm volatile("ldmatrix.sync.aligned.m8n8.x2.shared.b16 {%0,%1}, [%2];"
                 : "=r"(r[0]), "=r"(r[1]) : "r"(addr));
}
__device__ __forceinline__ void mma_bf16(float* d, const uint32_t* a, const uint32_t* b) {
    asm volatile(
        "mma.sync.aligned.m16n8k16.row.col.f32.bf16.bf16.f32 "
        "{%0,%1,%2,%3}, {%4,%5,%6,%7}, {%8,%9}, {%0,%1,%2,%3};"
        : "+f"(d[0]), "+f"(d[1]), "+f"(d[2]), "+f"(d[3])
        : "r"(a[0]), "r"(a[1]), "r"(a[2]), "r"(a[3]), "r"(b[0]), "r"(b[1]));
}

// ================= prep kernels =================
__global__ void detect_idx(const void* ei) {
    if (threadIdx.x == 0 && blockIdx.x == 0) {
        const unsigned long long* p = (const unsigned long long*)ei;
        int is64 = 1;
        for (int i = 0; i < 64; ++i)
            if (p[i] >= (unsigned long long)NNODES) { is64 = 0; break; }
        g_is64 = is64;
    }
}
__global__ void decode_idx(const void* ei) {
    int i = blockIdx.x * blockDim.x + threadIdx.x;
    size_t stride = (size_t)gridDim.x * blockDim.x;
    for (size_t j = i; j < (size_t)NNODES * DIM; j += stride) g_agg[j] = 0.f;
    for (size_t j = i; j < NNODES; j += stride) g_deg[j] = 0.f;
    if (i < NEDGES) {
        long long s, t;
        if (g_is64) { s = ((const long long*)ei)[i]; t = ((const long long*)ei)[NEDGES + i]; }
        else        { s = ((const int*)ei)[i];       t = ((const int*)ei)[NEDGES + i]; }
        if (s < 0) s = 0; if (s >= NNODES) s = NNODES - 1;
        if (t < 0) t = 0; if (t >= NNODES) t = NNODES - 1;
        g_src[i] = (int)s; g_tgt[i] = (int)t;
    }
}
__global__ void count_deg() {
    int i = blockIdx.x * blockDim.x + threadIdx.x;
    if (i < NEDGES) atomicAdd(&g_deg[g_tgt[i]], 1.f);
}
__global__ void prep_h(const float* __restrict__ h) {
    size_t id = (size_t)blockIdx.x * blockDim.x + threadIdx.x;  // over N*32 float4s
    if (id >= (size_t)NNODES * 32) return;
    float4 v = ((const float4*)h)[id];
    uint32_t h0, l0, h1, l1;
    cvt_pair(v.x, v.y, h0, l0);
    cvt_pair(v.z, v.w, h1, l1);
    ((uint2*)g_h_hi)[id] = make_uint2(h0, h1);
    ((uint2*)g_h_lo)[id] = make_uint2(l0, l1);
}
// swizzled B images: per K=64 chunk, 128 n-rows x 128B (k-major), XOR swizzle
__global__ void prep_w(const float* __restrict__ src, int sel, int nchunks) {
    int id = blockIdx.x * blockDim.x + threadIdx.x;
    if (id >= nchunks * 4096) return;
    uint32_t* dst_hi = (sel == 0) ? g_imgP_hi : (sel == 1) ? g_imgQ_hi : g_imgW_hi;
    uint32_t* dst_lo = (sel == 0) ? g_imgP_lo : (sel == 1) ? g_imgQ_lo : g_imgW_lo;
    int c = id >> 12, pos = id & 4095;
    int n = pos >> 5, kp = pos & 31;
    uint32_t off = n * 128 + kp * 4;
    uint32_t swz = off ^ ((off >> 3) & 0x70);   // == off ^ ((n&7)<<4)
    int k0 = c * 64 + kp * 2;
    float x = src[(size_t)k0 * DIM + n];
    float y = src[(size_t)(k0 + 1) * DIM + n];
    uint32_t hi, lo;
    cvt_pair(x, y, hi, lo);
    dst_hi[(c << 12) + (swz >> 2)] = hi;
    dst_lo[(c << 12) + (swz >> 2)] = lo;
}

// ================= tile building blocks =================
// copy one 16KB hi + 16KB lo B chunk; 128 threads x 8 uint4 each
__device__ __forceinline__ void copy_b(char* smem, const uint32_t* ih, const uint32_t* il,
                                       int ch, int tid) {
    const uint4* sh = (const uint4*)(ih + ((size_t)ch << 12));
    const uint4* sl = (const uint4*)(il + ((size_t)ch << 12));
    uint4* dh = (uint4*)(smem + B_HI_OFF);
    uint4* dl = (uint4*)(smem + B_LO_OFF);
#pragma unroll
    for (int i = 0; i < 8; ++i) {
        dh[i * 128 + tid] = sh[i * 128 + tid];
        dl[i * 128 + tid] = sl[i * 128 + tid];
    }
}
// gather half a row (4 uint4) of preconverted bf16 h into swizzled A tiles
__device__ __forceinline__ void fill_a_bf16(char* smem, int row, int half, int idx, int kc) {
    const uint4* sh = (const uint4*)g_h_hi + (size_t)idx * 16 + kc * 8 + half * 4;
    const uint4* sl = (const uint4*)g_h_lo + (size_t)idx * 16 + kc * 8 + half * 4;
    const uint32_t mask = (uint32_t)((row & 7) << 4);
#pragma unroll
    for (int i = 0; i < 4; ++i) {
        uint32_t off = (uint32_t)(row * 128) + (((uint32_t)((half * 4 + i) * 16)) ^ mask);
        *(uint4*)(smem + A_HI_OFF + off) = sh[i];
        *(uint4*)(smem + A_LO_OFF + off) = sl[i];
    }
}
// convert half a 64-float row chunk with scale into swizzled hi/lo A tiles
__device__ __forceinline__ void fill_a_f32(char* smem, int row, int half,
                                           const float* src, float sc) {
    const float4* s = (const float4*)src + half * 8;
    const uint32_t mask = (uint32_t)((row & 7) << 4);
#pragma unroll
    for (int i = 0; i < 4; ++i) {
        float4 a = s[2 * i], b = s[2 * i + 1];
        a.x *= sc; a.y *= sc; a.z *= sc; a.w *= sc;
        b.x *= sc; b.y *= sc; b.z *= sc; b.w *= sc;
        uint32_t h0, l0, h1, l1, h2, l2, h3, l3;
        cvt_pair(a.x, a.y, h0, l0); cvt_pair(a.z, a.w, h1, l1);
        cvt_pair(b.x, b.y, h2, l2); cvt_pair(b.z, b.w, h3, l3);
        uint32_t off = (uint32_t)(row * 128) + (((uint32_t)((half * 4 + i) * 16)) ^ mask);
        *(uint4*)(smem + A_HI_OFF + off) = make_uint4(h0, h1, h2, h3);
        *(uint4*)(smem + A_LO_OFF + off) = make_uint4(l0, l1, l2, l3);
    }
}
// per-thread address components: rowbase (swizzle-free bits >=7) + XORed column
struct Frag {
    uint32_t aBase, aMask, aC0;   // A: rowbase addr, swizzle mask, starting 16B-col
    uint32_t bBase, bMask, bC0;   // B
};
__device__ __forceinline__ Frag make_frag(uint32_t sb, int warp, int lane) {
    Frag f;
    int arow = warp * 16 + (lane & 7) + ((lane >> 3) & 1) * 8;
    f.aBase = sb + A_HI_OFF + (uint32_t)(arow * 128);
    f.aMask = (uint32_t)((arow & 7) << 4);
    f.aC0 = (uint32_t)(lane >> 4);            // 0 or 1 (k 0-7 vs 8-15)
    int brow = lane & 7;
    f.bBase = sb + B_HI_OFF + (uint32_t)(brow * 128);
    f.bMask = (uint32_t)(brow << 4);
    f.bC0 = (uint32_t)((lane >> 3) & 1);
    return f;
}
// consume one K=64 chunk: 4 k-steps x 16 n-frags x 3 split passes
__device__ __forceinline__ void compute_chunk(const Frag& f, float (*d)[4]) {
#pragma unroll
    for (int ks = 0; ks < 4; ++ks) {
        const uint32_t aoff = (((f.aC0 + 2 * ks) * 16) ^ f.aMask);
        uint32_t ah[4], al[4];
        ldsm_x4(ah, f.aBase + aoff);
        ldsm_x4(al, f.aBase + 8192 + aoff);
        const uint32_t boff = (((f.bC0 + 2 * ks) * 16) ^ f.bMask);
#pragma unroll
        for (int nf = 0; nf < 16; ++nf) {
            uint32_t bh[2], bl[2];
            ldsm_x2(bh, f.bBase + nf * 1024 + boff);
            ldsm_x2(bl, f.bBase + 16384 + nf * 1024 + boff);
            mma_bf16(d[nf], ah, bh);
            mma_bf16(d[nf], ah, bl);
            mma_bf16(d[nf], al, bh);
        }
    }
}

// ================= GEMM kernels =================
// K1: messages = relu([h_u, e] @ P + pb) -> atomic scatter-add into g_agg
__global__ __launch_bounds__(128) void k_msg(const float* __restrict__ e,
                                             const float* __restrict__ Pb) {
    extern __shared__ char smem[];
    const uint32_t sb = smem_u32(smem);
    const int tid = threadIdx.x, lane = tid & 31, warp = tid >> 5;
    const int e0 = blockIdx.x * 64;

    const int frow = tid >> 1, fhalf = tid & 1;
    const int feg = e0 + frow;
    const int fegc = (feg < NEDGES) ? feg : (NEDGES - 1);
    const int fsrc = (feg < NEDGES) ? g_src[feg] : 0;
    const Frag f = make_frag(sb, warp, lane);

    float d[16][4];
#pragma unroll
    for (int i = 0; i < 16; ++i)
#pragma unroll
        for (int j = 0; j < 4; ++j) d[i][j] = 0.f;

    // chunks: 0,1 = h_u halves (bf16 gather); 2,3 = e halves (f32 convert)
#pragma unroll 1
    for (int ch = 0; ch < 4; ++ch) {
        __syncthreads();
        if (ch < 2) fill_a_bf16(smem, frow, fhalf, fsrc, ch);
        else fill_a_f32(smem, frow, fhalf, e + (size_t)fegc * DIM + (ch - 2) * 64, 1.f);
        copy_b(smem, g_imgP_hi, g_imgP_lo, ch, tid);
        __syncthreads();
        compute_chunk(f, d);
    }

    const int r4 = lane >> 2, c2 = (lane & 3) * 2;
#pragma unroll
    for (int half = 0; half < 2; ++half) {
        const int lrow = warp * 16 + r4 + half * 8;
        const int eg = e0 + lrow;
        if (eg < NEDGES) {
            float* arow = g_agg + (size_t)__ldg(&g_tgt[eg]) * DIM;
#pragma unroll
            for (int nf = 0; nf < 16; ++nf) {
                float2 bias = __ldg((const float2*)(Pb + nf * 8 + c2));
                float2 v;
                v.x = fmaxf(d[nf][half * 2 + 0] + bias.x, 0.f);
                v.y = fmaxf(d[nf][half * 2 + 1] + bias.y, 0.f);
                atomicAdd((float2*)(arow + nf * 8 + c2), v);
            }
        }
    }
}

// K2: e_new = relu([e, h_u, h_v] @ W + wb)
__global__ __launch_bounds__(128) void k_upd(const float* __restrict__ e,
                                             const float* __restrict__ Wb,
                                             float* __restrict__ oute) {
    extern __shared__ char smem[];
    const uint32_t sb = smem_u32(smem);
    const int tid = threadIdx.x, lane = tid & 31, warp = tid >> 5;
    const int e0 = blockIdx.x * 64;

    const int frow = tid >> 1, fhalf = tid & 1;
    const int feg = e0 + frow;
    const int fegc = (feg < NEDGES) ? feg : (NEDGES - 1);
    const int fsrc = (feg < NEDGES) ? g_src[feg] : 0;
    const int ftgt = (feg < NEDGES) ? g_tgt[feg] : 0;
    const Frag f = make_frag(sb, warp, lane);

    float d[16][4];
#pragma unroll
    for (int i = 0; i < 16; ++i)
#pragma unroll
        for (int j = 0; j < 4; ++j) d[i][j] = 0.f;

    // chunks: 0,1 = e halves (f32); 2,3 = h_u (bf16); 4,5 = h_v (bf16)
#pragma unroll 1
    for (int ch = 0; ch < 6; ++ch) {
        __syncthreads();
        if (ch < 2) fill_a_f32(smem, frow, fhalf, e + (size_t)fegc * DIM + ch * 64, 1.f);
        else if (ch < 4) fill_a_bf16(smem, frow, fhalf, fsrc, ch - 2);
        else fill_a_bf16(smem, frow, fhalf, ftgt, ch - 4);
        copy_b(smem, g_imgW_hi, g_imgW_lo, ch, tid);
        __syncthreads();
        compute_chunk(f, d);
    }

    const int r4 = lane >> 2, c2 = (lane & 3) * 2;
#pragma unroll
    for (int half = 0; half < 2; ++half) {
        const int lrow = warp * 16 + r4 + half * 8;
        const int eg = e0 + lrow;
        if (eg < NEDGES) {
            float* orow = oute + (size_t)eg * DIM;
#pragma unroll
            for (int nf = 0; nf < 16; ++nf) {
                float2 bias = __ldg((const float2*)(Wb + nf * 8 + c2));
                float2 v;
                v.x = fmaxf(d[nf][half * 2 + 0] + bias.x, 0.f);
                v.y = fmaxf(d[nf][half * 2 + 1] + bias.y, 0.f);
                *(float2*)(orow + nf * 8 + c2) = v;
            }
        }
    }
}

// K3: h_new = relu([h, agg/deg] @ Q + qb)
__global__ __launch_bounds__(128) void k_node(const float* __restrict__ Qb,
                                              float* __restrict__ outh) {
    extern __shared__ char smem[];
    const uint32_t sb = smem_u32(smem);
    const int tid = threadIdx.x, lane = tid & 31, warp = tid >> 5;
    const int n0 = blockIdx.x * 64;

    const int frow = tid >> 1, fhalf = tid & 1;
    const int fng = n0 + frow;
    const int fnode = (fng < NNODES) ? fng : (NNODES - 1);
    const float finvd = 1.f / fmaxf(g_deg[fnode], 1.f);
    const Frag f = make_frag(sb, warp, lane);

    float d[16][4];
#pragma unroll
    for (int i = 0; i < 16; ++i)
#pragma unroll
        for (int j = 0; j < 4; ++j) d[i][j] = 0.f;

    // chunks: 0,1 = h (bf16); 2,3 = agg * invdeg (f32)
#pragma unroll 1
    for (int ch = 0; ch < 4; ++ch) {
        __syncthreads();
        if (ch < 2) fill_a_bf16(smem, frow, fhalf, fnode, ch);
        else fill_a_f32(smem, frow, fhalf, g_agg + (size_t)fnode * DIM + (ch - 2) * 64, finvd);
        copy_b(smem, g_imgQ_hi, g_imgQ_lo, ch, tid);
        __syncthreads();
        compute_chunk(f, d);
    }

    const int r4 = lane >> 2, c2 = (lane & 3) * 2;
#pragma unroll
    for (int half = 0; half < 2; ++half) {
        const int lrow = warp * 16 + r4 + half * 8;
        const int ng = n0 + lrow;
        if (ng < NNODES) {
            float* orow = outh + (size_t)ng * DIM;
#pragma unroll
            for (int nf = 0; nf < 16; ++nf) {
                float2 bias = __ldg((const float2*)(Qb + nf * 8 + c2));
                float2 v;
                v.x = fmaxf(d[nf][half * 2 + 0] + bias.x, 0.f);
                v.y = fmaxf(d[nf][half * 2 + 1] + bias.y, 0.f);
                *(float2*)(orow + nf * 8 + c2) = v;
            }
        }
    }
}

extern "C" void kernel_launch(void* const* d_in, const int* in_sizes, int n_in,
                              void* d_out, int out_size) {
    const float* h    = (const float*)d_in[0];
    const float* e    = (const float*)d_in[1];
    const void*  eidx = d_in[2];
    const float* Pw   = (const float*)d_in[3];
    const float* Pb   = (const float*)d_in[4];
    const float* Qw   = (const float*)d_in[5];
    const float* Qb   = (const float*)d_in[6];
    const float* Ww   = (const float*)d_in[7];
    const float* Wb   = (const float*)d_in[8];

    float* outh = (float*)d_out;
    float* oute = outh + (size_t)NNODES * DIM;

    const int dblocks = (NEDGES + 255) / 256;
    const int eg = (NEDGES + 63) / 64;   // 9766
    const int ng = (NNODES + 63) / 64;   // 1563

    detect_idx<<<1, 32>>>(eidx);
    decode_idx<<<dblocks, 256>>>(eidx);
    count_deg<<<dblocks, 256>>>();
    prep_h<<<(NNODES * 32 + 255) / 256, 256>>>(h);
    prep_w<<<64, 256>>>(Pw, 0, 4);
    prep_w<<<64, 256>>>(Qw, 1, 4);
    prep_w<<<96, 256>>>(Ww, 2, 6);
    k_msg<<<eg, 128, SMEM_BYTES>>>(e, Pb);
    k_node<<<ng, 128, SMEM_BYTES>>>(Qb, outh);
    k_upd<<<eg, 128, SMEM_BYTES>>>(e, Wb, oute);
}

// round 6
// speedup vs baseline: 2.7947x; 1.0315x over previous
#include <cuda_runtime.h>
#include <cstdint>

#define NNODES 100000
#define NEDGES 625000
#define DIM 128

// ---- smem layout (dynamic, exactly 48KB -> no opt-in attribute needed) ----
#define A_HI_OFF 0          // 64 rows x 128B (bf16 k-major, swizzled)
#define A_LO_OFF 8192
#define B_HI_OFF 16384      // 128 n-rows x 128B (k-major, swizzled)
#define B_LO_OFF 32768
#define SMEM_BYTES 49152

// ---- device scratch (allocation-free rule) ----
__device__ float g_agg[(size_t)NNODES * DIM];
__device__ float g_deg[NNODES];
__device__ int g_src[NEDGES];
__device__ int g_tgt[NEDGES];
__device__ int g_is64;
__device__ uint32_t g_h_hi[(size_t)NNODES * 64];   // bf16x2-packed h (hi part)
__device__ uint32_t g_h_lo[(size_t)NNODES * 64];
__device__ uint32_t g_imgP_hi[4 * 4096], g_imgP_lo[4 * 4096];  // swizzled weight images
__device__ uint32_t g_imgQ_hi[4 * 4096], g_imgQ_lo[4 * 4096];
__device__ uint32_t g_imgW_hi[6 * 4096], g_imgW_lo[6 * 4096];

// ================= helpers =================
__device__ __forceinline__ uint32_t smem_u32(const void* p) {
    uint32_t a;
    asm("{ .reg .u64 t; cvta.to.shared.u64 t, %1; cvt.u32.u64 %0, t; }" : "=r"(a) : "l"(p));
    return a;
}
// hi/lo bf16 split of packed pair (x,y); low 16 bits of word = bf16(x)
__device__ __forceinline__ void cvt_pair(float x, float y, uint32_t& hi, uint32_t& lo) {
    asm("cvt.rn.bf16x2.f32 %0, %2, %1;" : "=r"(hi) : "f"(x), "f"(y));
    float fx = __uint_as_float(hi << 16);
    float fy = __uint_as_float(hi & 0xffff0000u);
    float rx = x - fx, ry = y - fy;
    asm("cvt.rn.bf16x2.f32 %0, %2, %1;" : "=r"(lo) : "f"(rx), "f"(ry));
}
__device__ __forceinline__ void ldsm_x4(uint32_t* r, uint32_t addr) {
    asm volatile("ldmatrix.sync.aligned.m8n8.x4.shared.b16 {%0,%1,%2,%3}, [%4];"
                 : "=r"(r[0]), "=r"(r[1]), "=r"(r[2]), "=r"(r[3]) : "r"(addr));
}
__device__ __forceinline__ void mma_bf16(float* d, const uint32_t* a, const uint32_t* b) {
    asm volatile(
        "mma.sync.aligned.m16n8k16.row.col.f32.bf16.bf16.f32 "
        "{%0,%1,%2,%3}, {%4,%5,%6,%7}, {%8,%9}, {%0,%1,%2,%3};"
        : "+f"(d[0]), "+f"(d[1]), "+f"(d[2]), "+f"(d[3])
        : "r"(a[0]), "r"(a[1]), "r"(a[2]), "r"(a[3]), "r"(b[0]), "r"(b[1]));
}

// ================= prep kernels =================
__global__ void detect_idx(const void* ei) {
    if (threadIdx.x == 0 && blockIdx.x == 0) {
        const unsigned long long* p = (const unsigned long long*)ei;
        int is64 = 1;
        for (int i = 0; i < 64; ++i)
            if (p[i] >= (unsigned long long)NNODES) { is64 = 0; break; }
        g_is64 = is64;
    }
}
__global__ void decode_idx(const void* ei) {
    int i = blockIdx.x * blockDim.x + threadIdx.x;
    size_t stride = (size_t)gridDim.x * blockDim.x;
    for (size_t j = i; j < (size_t)NNODES * DIM; j += stride) g_agg[j] = 0.f;
    for (size_t j = i; j < NNODES; j += stride) g_deg[j] = 0.f;
    if (i < NEDGES) {
        long long s, t;
        if (g_is64) { s = ((const long long*)ei)[i]; t = ((const long long*)ei)[NEDGES + i]; }
        else        { s = ((const int*)ei)[i];       t = ((const int*)ei)[NEDGES + i]; }
        if (s < 0) s = 0; if (s >= NNODES) s = NNODES - 1;
        if (t < 0) t = 0; if (t >= NNODES) t = NNODES - 1;
        g_src[i] = (int)s; g_tgt[i] = (int)t;
    }
}
__global__ void count_deg() {
    int i = blockIdx.x * blockDim.x + threadIdx.x;
    if (i < NEDGES) atomicAdd(&g_deg[g_tgt[i]], 1.f);
}
__global__ void prep_h(const float* __restrict__ h) {
    size_t id = (size_t)blockIdx.x * blockDim.x + threadIdx.x;  // over N*32 float4s
    if (id >= (size_t)NNODES * 32) return;
    float4 v = ((const float4*)h)[id];
    uint32_t h0, l0, h1, l1;
    cvt_pair(v.x, v.y, h0, l0);
    cvt_pair(v.z, v.w, h1, l1);
    ((uint2*)g_h_hi)[id] = make_uint2(h0, h1);
    ((uint2*)g_h_lo)[id] = make_uint2(l0, l1);
}
// swizzled B images: per K=64 chunk, 128 n-rows x 128B (k-major), XOR swizzle
__global__ void prep_w(const float* __restrict__ src, int sel, int nchunks) {
    int id = blockIdx.x * blockDim.x + threadIdx.x;
    if (id >= nchunks * 4096) return;
    uint32_t* dst_hi = (sel == 0) ? g_imgP_hi : (sel == 1) ? g_imgQ_hi : g_imgW_hi;
    uint32_t* dst_lo = (sel == 0) ? g_imgP_lo : (sel == 1) ? g_imgQ_lo : g_imgW_lo;
    int c = id >> 12, pos = id & 4095;
    int n = pos >> 5, kp = pos & 31;
    uint32_t off = n * 128 + kp * 4;
    uint32_t swz = off ^ ((off >> 3) & 0x70);   // == off ^ ((n&7)<<4)
    int k0 = c * 64 + kp * 2;
    float x = src[(size_t)k0 * DIM + n];
    float y = src[(size_t)(k0 + 1) * DIM + n];
    uint32_t hi, lo;
    cvt_pair(x, y, hi, lo);
    dst_hi[(c << 12) + (swz >> 2)] = hi;
    dst_lo[(c << 12) + (swz >> 2)] = lo;
}

// ================= tile building blocks =================
// copy one 16KB hi + 16KB lo B chunk; 128 threads x 8 uint4 each
__device__ __forceinline__ void copy_b(char* smem, const uint32_t* ih, const uint32_t* il,
                                       int ch, int tid) {
    const uint4* sh = (const uint4*)(ih + ((size_t)ch << 12));
    const uint4* sl = (const uint4*)(il + ((size_t)ch << 12));
    uint4* dh = (uint4*)(smem + B_HI_OFF);
    uint4* dl = (uint4*)(smem + B_LO_OFF);
#pragma unroll
    for (int i = 0; i < 8; ++i) {
        dh[i * 128 + tid] = sh[i * 128 + tid];
        dl[i * 128 + tid] = sl[i * 128 + tid];
    }
}
// gather half a row (4 uint4) of preconverted bf16 h into swizzled A tiles
__device__ __forceinline__ void fill_a_bf16(char* smem, int row, int half, int idx, int kc) {
    const uint4* sh = (const uint4*)g_h_hi + (size_t)idx * 16 + kc * 8 + half * 4;
    const uint4* sl = (const uint4*)g_h_lo + (size_t)idx * 16 + kc * 8 + half * 4;
    const uint32_t mask = (uint32_t)((row & 7) << 4);
#pragma unroll
    for (int i = 0; i < 4; ++i) {
        uint32_t off = (uint32_t)(row * 128) + (((uint32_t)((half * 4 + i) * 16)) ^ mask);
        *(uint4*)(smem + A_HI_OFF + off) = sh[i];
        *(uint4*)(smem + A_LO_OFF + off) = sl[i];
    }
}
// convert half a 64-float row chunk with scale into swizzled hi/lo A tiles
__device__ __forceinline__ void fill_a_f32(char* smem, int row, int half,
                                           const float* src, float sc) {
    const float4* s = (const float4*)src + half * 8;
    const uint32_t mask = (uint32_t)((row & 7) << 4);
#pragma unroll
    for (int i = 0; i < 4; ++i) {
        float4 a = s[2 * i], b = s[2 * i + 1];
        a.x *= sc; a.y *= sc; a.z *= sc; a.w *= sc;
        b.x *= sc; b.y *= sc; b.z *= sc; b.w *= sc;
        uint32_t h0, l0, h1, l1, h2, l2, h3, l3;
        cvt_pair(a.x, a.y, h0, l0); cvt_pair(a.z, a.w, h1, l1);
        cvt_pair(b.x, b.y, h2, l2); cvt_pair(b.z, b.w, h3, l3);
        uint32_t off = (uint32_t)(row * 128) + (((uint32_t)((half * 4 + i) * 16)) ^ mask);
        *(uint4*)(smem + A_HI_OFF + off) = make_uint4(h0, h1, h2, h3);
        *(uint4*)(smem + A_LO_OFF + off) = make_uint4(l0, l1, l2, l3);
    }
}
// per-thread address components.
// Warp w owns ALL 64 M-rows x N-slice [w*32, w*32+32).
// A ldmatrix.x4: lanes 0-15 -> rows (mf*16 + lane&15); lanes 16-31 -> k-half.
// B ldmatrix.x4: loads an nf PAIR: lanes 0-15 -> first nf (8 n-rows x 2 k-halves),
//                lanes 16-31 -> +1024B = next 8 n-rows (nf+1).
struct Frag {
    uint32_t aBase, aMask, aC0;
    uint32_t bBase, bMask, bC0;
};
__device__ __forceinline__ Frag make_frag(uint32_t sb, int warp, int lane) {
    Frag f;
    f.aBase = sb + A_HI_OFF + (uint32_t)((lane & 15) * 128);
    f.aMask = (uint32_t)((lane & 7) << 4);
    f.aC0 = (uint32_t)(lane >> 4);            // 0 or 1 (k 0-7 vs 8-15)
    f.bBase = sb + B_HI_OFF + (uint32_t)(warp * 4096 + (lane & 7) * 128 +
                                         ((lane >> 4) & 1) * 1024);
    f.bMask = (uint32_t)((lane & 7) << 4);
    f.bC0 = (uint32_t)((lane >> 3) & 1);
    return f;
}
// consume one K=64 chunk: 4 ks x (4 Mfrags x 4 local nf) x 3 split passes
// d[mf][nfl][4]
__device__ __forceinline__ void compute_chunk(const Frag& f, float (*d)[4][4]) {
#pragma unroll
    for (int ks = 0; ks < 4; ++ks) {
        const uint32_t aoff = (((f.aC0 + 2 * ks) * 16) ^ f.aMask);
        uint32_t ah[4][4], al[4][4];
#pragma unroll
        for (int mf = 0; mf < 4; ++mf) {
            ldsm_x4(ah[mf], f.aBase + mf * 2048 + aoff);
            ldsm_x4(al[mf], f.aBase + 8192 + mf * 2048 + aoff);
        }
        const uint32_t boff = (((f.bC0 + 2 * ks) * 16) ^ f.bMask);
#pragma unroll
        for (int p = 0; p < 2; ++p) {            // nf pairs (2p, 2p+1) within slice
            uint32_t bh[4], bl[4];
            ldsm_x4(bh, f.bBase + p * 2048 + boff);
            ldsm_x4(bl, f.bBase + 16384 + p * 2048 + boff);
#pragma unroll
            for (int sub = 0; sub < 2; ++sub) {
#pragma unroll
                for (int mf = 0; mf < 4; ++mf) {
                    float* acc = d[mf][p * 2 + sub];
                    mma_bf16(acc, ah[mf], bh + 2 * sub);
                    mma_bf16(acc, ah[mf], bl + 2 * sub);
                    mma_bf16(acc, al[mf], bh + 2 * sub);
                }
            }
        }
    }
}

// ================= GEMM kernels =================
// K1: messages = relu([h_u, e] @ P + pb) -> atomic scatter-add into g_agg
__global__ __launch_bounds__(128) void k_msg(const float* __restrict__ e,
                                             const float* __restrict__ Pb) {
    extern __shared__ char smem[];
    const uint32_t sb = smem_u32(smem);
    const int tid = threadIdx.x, lane = tid & 31, warp = tid >> 5;
    const int e0 = blockIdx.x * 64;

    const int frow = tid >> 1, fhalf = tid & 1;
    const int feg = e0 + frow;
    const int fegc = (feg < NEDGES) ? feg : (NEDGES - 1);
    const int fsrc = (feg < NEDGES) ? g_src[feg] : 0;
    const Frag f = make_frag(sb, warp, lane);

    float d[4][4][4];
#pragma unroll
    for (int i = 0; i < 4; ++i)
#pragma unroll
        for (int j = 0; j < 4; ++j)
#pragma unroll
            for (int k = 0; k < 4; ++k) d[i][j][k] = 0.f;

    // chunks: 0,1 = h_u halves (bf16 gather); 2,3 = e halves (f32 convert)
#pragma unroll 1
    for (int ch = 0; ch < 4; ++ch) {
        __syncthreads();
        if (ch < 2) fill_a_bf16(smem, frow, fhalf, fsrc, ch);
        else fill_a_f32(smem, frow, fhalf, e + (size_t)fegc * DIM + (ch - 2) * 64, 1.f);
        copy_b(smem, g_imgP_hi, g_imgP_lo, ch, tid);
        __syncthreads();
        compute_chunk(f, d);
    }

    const int r4 = lane >> 2, c2 = (lane & 3) * 2;
#pragma unroll
    for (int mf = 0; mf < 4; ++mf) {
#pragma unroll
        for (int half = 0; half < 2; ++half) {
            const int eg = e0 + mf * 16 + r4 + half * 8;
            if (eg < NEDGES) {
                float* arow = g_agg + (size_t)__ldg(&g_tgt[eg]) * DIM;
#pragma unroll
                for (int nfl = 0; nfl < 4; ++nfl) {
                    const int col = warp * 32 + nfl * 8 + c2;
                    float2 bias = __ldg((const float2*)(Pb + col));
                    float2 v;
                    v.x = fmaxf(d[mf][nfl][half * 2 + 0] + bias.x, 0.f);
                    v.y = fmaxf(d[mf][nfl][half * 2 + 1] + bias.y, 0.f);
                    atomicAdd((float2*)(arow + col), v);
                }
            }
        }
    }
}

// K2: e_new = relu([e, h_u, h_v] @ W + wb)
__global__ __launch_bounds__(128) void k_upd(const float* __restrict__ e,
                                             const float* __restrict__ Wb,
                                             float* __restrict__ oute) {
    extern __shared__ char smem[];
    const uint32_t sb = smem_u32(smem);
    const int tid = threadIdx.x, lane = tid & 31, warp = tid >> 5;
    const int e0 = blockIdx.x * 64;

    const int frow = tid >> 1, fhalf = tid & 1;
    const int feg = e0 + frow;
    const int fegc = (feg < NEDGES) ? feg : (NEDGES - 1);
    const int fsrc = (feg < NEDGES) ? g_src[feg] : 0;
    const int ftgt = (feg < NEDGES) ? g_tgt[feg] : 0;
    const Frag f = make_frag(sb, warp, lane);

    float d[4][4][4];
#pragma unroll
    for (int i = 0; i < 4; ++i)
#pragma unroll
        for (int j = 0; j < 4; ++j)
#pragma unroll
            for (int k = 0; k < 4; ++k) d[i][j][k] = 0.f;

    // chunks: 0,1 = e halves (f32); 2,3 = h_u (bf16); 4,5 = h_v (bf16)
#pragma unroll 1
    for (int ch = 0; ch < 6; ++ch) {
        __syncthreads();
        if (ch < 2) fill_a_f32(smem, frow, fhalf, e + (size_t)fegc * DIM + ch * 64, 1.f);
        else if (ch < 4) fill_a_bf16(smem, frow, fhalf, fsrc, ch - 2);
        else fill_a_bf16(smem, frow, fhalf, ftgt, ch - 4);
        copy_b(smem, g_imgW_hi, g_imgW_lo, ch, tid);
        __syncthreads();
        compute_chunk(f, d);
    }

    const int r4 = lane >> 2, c2 = (lane & 3) * 2;
#pragma unroll
    for (int mf = 0; mf < 4; ++mf) {
#pragma unroll
        for (int half = 0; half < 2; ++half) {
            const int eg = e0 + mf * 16 + r4 + half * 8;
            if (eg < NEDGES) {
                float* orow = oute + (size_t)eg * DIM;
#pragma unroll
                for (int nfl = 0; nfl < 4; ++nfl) {
                    const int col = warp * 32 + nfl * 8 + c2;
                    float2 bias = __ldg((const float2*)(Wb + col));
                    float2 v;
                    v.x = fmaxf(d[mf][nfl][half * 2 + 0] + bias.x, 0.f);
                    v.y = fmaxf(d[mf][nfl][half * 2 + 1] + bias.y, 0.f);
                    *(float2*)(orow + col) = v;
                }
            }
        }
    }
}

// K3: h_new = relu([h, agg/deg] @ Q + qb)
__global__ __launch_bounds__(128) void k_node(const float* __restrict__ Qb,
                                              float* __restrict__ outh) {
    extern __shared__ char smem[];
    const uint32_t sb = smem_u32(smem);
    const int tid = threadIdx.x, lane = tid & 31, warp = tid >> 5;
    const int n0 = blockIdx.x * 64;

    const int frow = tid >> 1, fhalf = tid & 1;
    const int fng = n0 + frow;
    const int fnode = (fng < NNODES) ? fng : (NNODES - 1);
    const float finvd = 1.f / fmaxf(g_deg[fnode], 1.f);
    const Frag f = make_frag(sb, warp, lane);

    float d[4][4][4];
#pragma unroll
    for (int i = 0; i < 4; ++i)
#pragma unroll
        for (int j = 0; j < 4; ++j)
#pragma unroll
            for (int k = 0; k < 4; ++k) d[i][j][k] = 0.f;

    // chunks: 0,1 = h (bf16); 2,3 = agg * invdeg (f32)
#pragma unroll 1
    for (int ch = 0; ch < 4; ++ch) {
        __syncthreads();
        if (ch < 2) fill_a_bf16(smem, frow, fhalf, fnode, ch);
        else fill_a_f32(smem, frow, fhalf, g_agg + (size_t)fnode * DIM + (ch - 2) * 64, finvd);
        copy_b(smem, g_imgQ_hi, g_imgQ_lo, ch, tid);
        __syncthreads();
        compute_chunk(f, d);
    }

    const int r4 = lane >> 2, c2 = (lane & 3) * 2;
#pragma unroll
    for (int mf = 0; mf < 4; ++mf) {
#pragma unroll
        for (int half = 0; half < 2; ++half) {
            const int ng = n0 + mf * 16 + r4 + half * 8;
            if (ng < NNODES) {
                float* orow = outh + (size_t)ng * DIM;
#pragma unroll
                for (int nfl = 0; nfl < 4; ++nfl) {
                    const int col = warp * 32 + nfl * 8 + c2;
                    float2 bias = __ldg((const float2*)(Qb + col));
                    float2 v;
                    v.x = fmaxf(d[mf][nfl][half * 2 + 0] + bias.x, 0.f);
                    v.y = fmaxf(d[mf][nfl][half * 2 + 1] + bias.y, 0.f);
                    *(float2*)(orow + col) = v;
                }
            }
        }
    }
}

extern "C" void kernel_launch(void* const* d_in, const int* in_sizes, int n_in,
                              void* d_out, int out_size) {
    const float* h    = (const float*)d_in[0];
    const float* e    = (const float*)d_in[1];
    const void*  eidx = d_in[2];
    const float* Pw   = (const float*)d_in[3];
    const float* Pb   = (const float*)d_in[4];
    const float* Qw   = (const float*)d_in[5];
    const float* Qb   = (const float*)d_in[6];
    const float* Ww   = (const float*)d_in[7];
    const float* Wb   = (const float*)d_in[8];

    float* outh = (float*)d_out;
    float* oute = outh + (size_t)NNODES * DIM;

    const int dblocks = (NEDGES + 255) / 256;
    const int eg = (NEDGES + 63) / 64;   // 9766
    const int ng = (NNODES + 63) / 64;   // 1563

    detect_idx<<<1, 32>>>(eidx);
    decode_idx<<<dblocks, 256>>>(eidx);
    count_deg<<<dblocks, 256>>>();
    prep_h<<<(NNODES * 32 + 255) / 256, 256>>>(h);
    prep_w<<<64, 256>>>(Pw, 0, 4);
    prep_w<<<64, 256>>>(Qw, 1, 4);
    prep_w<<<96, 256>>>(Ww, 2, 6);
    k_msg<<<eg, 128, SMEM_BYTES>>>(e, Pb);
    k_node<<<ng, 128, SMEM_BYTES>>>(Qb, outh);
    k_upd<<<eg, 128, SMEM_BYTES>>>(e, Wb, oute);
}